// round 3
// baseline (speedup 1.0000x reference)
#include <cuda_runtime.h>
#include <cuda_bf16.h>
#include <cstdint>

// ---------------------------------------------------------------------------
// Problem: out[b,:] = A^{-1} @ x[b,:]  for b in [0, 2e6), N = 10.
//   K1: one-warp fp64 Gauss-Jordan (partial pivoting) -> invA (fp32).
//   K2: 2 rows per thread, LDG.128/STG.128 streaming, scalar FMA,
//       weights broadcast from shared memory.
// Memory floor: 160 MB stream ~ 25 us. FMA pipe ~21k cyc/SM < 25.4k memory
// cyc/SM, so the kernel stays DRAM-bound with plain scalar FFMA.
// ---------------------------------------------------------------------------

__device__ float g_invA[100];   // A^{-1}, row-major

// ---------------------------- Kernel 1: inversion ---------------------------

__global__ void invert10_kernel(const float* __restrict__ A) {
    const unsigned FULL = 0xffffffffu;
    const int lane = threadIdx.x;

    double row[20];
#pragma unroll
    for (int j = 0; j < 20; j++) row[j] = 0.0;
    if (lane < 10) {
#pragma unroll
        for (int j = 0; j < 10; j++) row[j] = (double)A[lane * 10 + j];
#pragma unroll
        for (int j = 0; j < 10; j++) row[10 + j] = (lane == j) ? 1.0 : 0.0;
    }

#pragma unroll
    for (int k = 0; k < 10; k++) {
        // Partial-pivot argmax over |row[k]| among lanes k..9 (deterministic tiebreak).
        double v = (lane >= k && lane < 10) ? fabs(row[k]) : -1.0;
        int best = lane;
#pragma unroll
        for (int off = 16; off; off >>= 1) {
            double ov = __shfl_xor_sync(FULL, v, off);
            int    ob = __shfl_xor_sync(FULL, best, off);
            if (ov > v || (ov == v && ob < best)) { v = ov; best = ob; }
        }
        const int piv = best;  // uniform across warp

        // Swap rows k <-> piv via shuffles.
#pragma unroll
        for (int j = 0; j < 20; j++) {
            double vk = __shfl_sync(FULL, row[j], k);
            double vp = __shfl_sync(FULL, row[j], piv);
            if (piv != k) {
                if (lane == k)   row[j] = vp;
                if (lane == piv) row[j] = vk;
            }
        }

        // Broadcast pivot row, eliminate.
        double pr[20];
#pragma unroll
        for (int j = 0; j < 20; j++) pr[j] = __shfl_sync(FULL, row[j], k);
        const double pinv = 1.0 / pr[k];
        if (lane < 10) {
            if (lane == k) {
#pragma unroll
                for (int j = 0; j < 20; j++) row[j] *= pinv;
            } else {
                const double f = row[k] * pinv;
#pragma unroll
                for (int j = 0; j < 20; j++) row[j] -= f * pr[j];
            }
        }
    }

    if (lane < 10) {
#pragma unroll
        for (int j = 0; j < 10; j++) g_invA[lane * 10 + j] = (float)row[10 + j];
    }
}

// ------------------------- Kernel 2: streaming solve ------------------------
// One thread handles rows (2*idx, 2*idx+1): 80 bytes = 5x float4 in/out.

__global__ void __launch_bounds__(256) solve_kernel(
    const float4* __restrict__ x4, float4* __restrict__ o4, int npairs) {

    __shared__ float sw[100];
    const int t = threadIdx.x;
    if (t < 100) sw[t] = g_invA[t];
    __syncthreads();

    const int idx = blockIdx.x * blockDim.x + t;
    if (idx >= npairs) return;

    const float4* p = x4 + (size_t)idx * 5;
    float4 v0 = __ldcs(p + 0);
    float4 v1 = __ldcs(p + 1);
    float4 v2 = __ldcs(p + 2);
    float4 v3 = __ldcs(p + 3);
    float4 v4 = __ldcs(p + 4);

    const float a0[10] = { v0.x, v0.y, v0.z, v0.w, v1.x, v1.y, v1.z, v1.w, v2.x, v2.y };
    const float a1[10] = { v2.z, v2.w, v3.x, v3.y, v3.z, v3.w, v4.x, v4.y, v4.z, v4.w };

    float r0[10], r1[10];
#pragma unroll
    for (int i = 0; i < 10; i++) {
        float acc0 = 0.0f;
        float acc1 = 0.0f;
#pragma unroll
        for (int j = 0; j < 10; j++) {
            const float w = sw[i * 10 + j];   // uniform across warp -> LDS broadcast
            acc0 = fmaf(w, a0[j], acc0);
            acc1 = fmaf(w, a1[j], acc1);
        }
        r0[i] = acc0;
        r1[i] = acc1;
    }

    float4* q = o4 + (size_t)idx * 5;
    __stcs(q + 0, make_float4(r0[0], r0[1], r0[2], r0[3]));
    __stcs(q + 1, make_float4(r0[4], r0[5], r0[6], r0[7]));
    __stcs(q + 2, make_float4(r0[8], r0[9], r1[0], r1[1]));
    __stcs(q + 3, make_float4(r1[2], r1[3], r1[4], r1[5]));
    __stcs(q + 4, make_float4(r1[6], r1[7], r1[8], r1[9]));
}

// ----------------------- Tail: odd leftover row (safety) --------------------

__global__ void tail_kernel(const float* __restrict__ x, float* __restrict__ out,
                            int rowstart, int nrows) {
    int r = rowstart + blockIdx.x * blockDim.x + threadIdx.x;
    if (r >= nrows) return;
    float a[10];
#pragma unroll
    for (int j = 0; j < 10; j++) a[j] = x[r * 10 + j];
#pragma unroll
    for (int i = 0; i < 10; i++) {
        float acc = 0.f;
#pragma unroll
        for (int j = 0; j < 10; j++) acc = fmaf(g_invA[i * 10 + j], a[j], acc);
        out[r * 10 + i] = acc;
    }
}

// ---------------------------------------------------------------------------

extern "C" void kernel_launch(void* const* d_in, const int* in_sizes, int n_in,
                              void* d_out, int out_size) {
    const float* x = (const float*)d_in[0];   // [B, 10]
    const float* A = (const float*)d_in[1];   // [10, 10]
    float* out = (float*)d_out;

    const int n_elems = in_sizes[0];
    const int nrows   = n_elems / 10;
    const int npairs  = nrows / 2;

    invert10_kernel<<<1, 32>>>(A);

    if (npairs > 0) {
        const int threads = 256;
        const int blocks  = (npairs + threads - 1) / threads;
        solve_kernel<<<blocks, threads>>>((const float4*)x, (float4*)out, npairs);
    }
    if (nrows & 1) {
        tail_kernel<<<1, 32>>>(x, out, npairs * 2, nrows);
    }
}

// round 5
// speedup vs baseline: 1.0016x; 1.0016x over previous
#include <cuda_runtime.h>
#include <cuda_bf16.h>
#include <cstdint>

// ---------------------------------------------------------------------------
// out[b,:] = A^{-1} @ x[b,:],  B = 2e6, N = 10.
//   K1: one-warp fp32 Gauss-Jordan (partial pivot) + Newton polish -> invA.
//   K2: per-warp smem staging -> fully coalesced LDG.128/STG.128 both ways,
//       2 rows/thread, scalar FMA with weights broadcast from shared.
// ---------------------------------------------------------------------------

__device__ float g_invA[100];   // A^{-1}, row-major

// ---------------------------- Kernel 1: inversion ---------------------------

__global__ void invert10_kernel(const float* __restrict__ A) {
    const unsigned FULL = 0xffffffffu;
    const int lane = threadIdx.x;

    float arow[10];   // original A row (for Newton polish)
    float row[20];    // augmented [A | I]
#pragma unroll
    for (int j = 0; j < 10; j++) arow[j] = 0.f;
#pragma unroll
    for (int j = 0; j < 20; j++) row[j] = 0.f;
    if (lane < 10) {
#pragma unroll
        for (int j = 0; j < 10; j++) { arow[j] = A[lane * 10 + j]; row[j] = arow[j]; }
#pragma unroll
        for (int j = 0; j < 10; j++) row[10 + j] = (lane == j) ? 1.f : 0.f;
    }

#pragma unroll
    for (int k = 0; k < 10; k++) {
        // argmax |row[k]| over lanes k..9
        float v = (lane >= k && lane < 10) ? fabsf(row[k]) : -1.f;
        int best = lane;
#pragma unroll
        for (int off = 16; off; off >>= 1) {
            float ov = __shfl_xor_sync(FULL, v, off);
            int   ob = __shfl_xor_sync(FULL, best, off);
            if (ov > v || (ov == v && ob < best)) { v = ov; best = ob; }
        }
        const int piv = best;

        // swap rows k <-> piv
#pragma unroll
        for (int j = 0; j < 20; j++) {
            float vk = __shfl_sync(FULL, row[j], k);
            float vp = __shfl_sync(FULL, row[j], piv);
            if (piv != k) {
                if (lane == k)   row[j] = vp;
                if (lane == piv) row[j] = vk;
            }
        }

        // eliminate
        float pr[20];
#pragma unroll
        for (int j = 0; j < 20; j++) pr[j] = __shfl_sync(FULL, row[j], k);
        const float pinv = 1.f / pr[k];
        if (lane < 10) {
            if (lane == k) {
#pragma unroll
                for (int j = 0; j < 20; j++) row[j] *= pinv;
            } else {
                const float f = row[k] * pinv;
#pragma unroll
                for (int j = 0; j < 20; j++) row[j] = fmaf(-f, pr[j], row[j]);
            }
        }
    }

    float x0[10];   // X0 row = row of approximate inverse
#pragma unroll
    for (int j = 0; j < 10; j++) x0[j] = row[10 + j];

    // Newton polish: X1 = X0 (2I - A X0).
    // E[r][j] = (r==j?2:0) - sum_k arow[k] * X0[k][j]
    float e[10];
#pragma unroll
    for (int j = 0; j < 10; j++) e[j] = (lane == j) ? 2.f : 0.f;
#pragma unroll
    for (int k = 0; k < 10; k++) {
        const float ak = arow[k];
#pragma unroll
        for (int j = 0; j < 10; j++) {
            float xkj = __shfl_sync(FULL, x0[j], k);
            e[j] = fmaf(-ak, xkj, e[j]);
        }
    }
    // X1[r][j] = sum_k X0[r][k] * E[k][j]
    float x1[10];
#pragma unroll
    for (int j = 0; j < 10; j++) x1[j] = 0.f;
#pragma unroll
    for (int k = 0; k < 10; k++) {
        const float xk = x0[k];
#pragma unroll
        for (int j = 0; j < 10; j++) {
            float ekj = __shfl_sync(FULL, e[j], k);
            x1[j] = fmaf(xk, ekj, x1[j]);
        }
    }

    if (lane < 10) {
#pragma unroll
        for (int j = 0; j < 10; j++) g_invA[lane * 10 + j] = x1[j];
    }
}

// ------------------------- Kernel 2: streaming solve ------------------------
// Warp tile: 32 pairs = 64 rows = 2560 B = 160 float4. Coalesced global access
// both directions; per-warp smem region for redistribution.

__global__ void __launch_bounds__(256, 4) solve_kernel(
    const float4* __restrict__ x4, float4* __restrict__ o4, int npairs) {

    __shared__ float4 sbuf[8 * 160];   // 20 KB: one 2560 B region per warp
    __shared__ float  sw[100];

    const int t = threadIdx.x;
    if (t < 100) sw[t] = g_invA[t];
    __syncthreads();

    const int warp = t >> 5;
    const int lane = t & 31;
    const int pairBase = blockIdx.x * 256 + warp * 32;   // blockDim=256 -> 8 warps * 32 pairs
    float4* wb = sbuf + warp * 160;

    if (pairBase + 32 <= npairs) {
        const size_t f4base = (size_t)pairBase * 5;

        // coalesced load -> smem
#pragma unroll
        for (int s = 0; s < 5; s++)
            wb[lane + 32 * s] = __ldcs(x4 + f4base + lane + 32 * s);
        __syncwarp();

        // my 2 rows from smem (stride 80 B, conflict-free per 8-lane phase)
        float4 v0 = wb[5 * lane + 0];
        float4 v1 = wb[5 * lane + 1];
        float4 v2 = wb[5 * lane + 2];
        float4 v3 = wb[5 * lane + 3];
        float4 v4 = wb[5 * lane + 4];

        const float a0[10] = { v0.x, v0.y, v0.z, v0.w, v1.x, v1.y, v1.z, v1.w, v2.x, v2.y };
        const float a1[10] = { v2.z, v2.w, v3.x, v3.y, v3.z, v3.w, v4.x, v4.y, v4.z, v4.w };

        float r0[10], r1[10];
#pragma unroll
        for (int i = 0; i < 10; i++) {
            float acc0 = 0.f, acc1 = 0.f;
#pragma unroll
            for (int j = 0; j < 10; j++) {
                const float w = sw[i * 10 + j];   // uniform -> LDS broadcast
                acc0 = fmaf(w, a0[j], acc0);
                acc1 = fmaf(w, a1[j], acc1);
            }
            r0[i] = acc0;
            r1[i] = acc1;
        }

        // results back into MY region (only I read/wrote it since syncwarp)
        wb[5 * lane + 0] = make_float4(r0[0], r0[1], r0[2], r0[3]);
        wb[5 * lane + 1] = make_float4(r0[4], r0[5], r0[6], r0[7]);
        wb[5 * lane + 2] = make_float4(r0[8], r0[9], r1[0], r1[1]);
        wb[5 * lane + 3] = make_float4(r1[2], r1[3], r1[4], r1[5]);
        wb[5 * lane + 4] = make_float4(r1[6], r1[7], r1[8], r1[9]);
        __syncwarp();

        // coalesced smem -> global
#pragma unroll
        for (int s = 0; s < 5; s++)
            __stcs(o4 + f4base + lane + 32 * s, wb[lane + 32 * s]);
    } else {
        // partial warp tile (at most the last 1-2 warps of the grid): direct path
        const int idx = pairBase + lane;
        if (idx < npairs) {
            const float4* p = x4 + (size_t)idx * 5;
            float4 v0 = __ldcs(p + 0);
            float4 v1 = __ldcs(p + 1);
            float4 v2 = __ldcs(p + 2);
            float4 v3 = __ldcs(p + 3);
            float4 v4 = __ldcs(p + 4);

            const float a0[10] = { v0.x, v0.y, v0.z, v0.w, v1.x, v1.y, v1.z, v1.w, v2.x, v2.y };
            const float a1[10] = { v2.z, v2.w, v3.x, v3.y, v3.z, v3.w, v4.x, v4.y, v4.z, v4.w };

            float r0[10], r1[10];
#pragma unroll
            for (int i = 0; i < 10; i++) {
                float acc0 = 0.f, acc1 = 0.f;
#pragma unroll
                for (int j = 0; j < 10; j++) {
                    const float w = sw[i * 10 + j];
                    acc0 = fmaf(w, a0[j], acc0);
                    acc1 = fmaf(w, a1[j], acc1);
                }
                r0[i] = acc0;
                r1[i] = acc1;
            }

            float4* q = o4 + (size_t)idx * 5;
            __stcs(q + 0, make_float4(r0[0], r0[1], r0[2], r0[3]));
            __stcs(q + 1, make_float4(r0[4], r0[5], r0[6], r0[7]));
            __stcs(q + 2, make_float4(r0[8], r0[9], r1[0], r1[1]));
            __stcs(q + 3, make_float4(r1[2], r1[3], r1[4], r1[5]));
            __stcs(q + 4, make_float4(r1[6], r1[7], r1[8], r1[9]));
        }
    }
}

// ----------------------- Tail: odd leftover row (safety) --------------------

__global__ void tail_kernel(const float* __restrict__ x, float* __restrict__ out,
                            int rowstart, int nrows) {
    int r = rowstart + blockIdx.x * blockDim.x + threadIdx.x;
    if (r >= nrows) return;
    float a[10];
#pragma unroll
    for (int j = 0; j < 10; j++) a[j] = x[r * 10 + j];
#pragma unroll
    for (int i = 0; i < 10; i++) {
        float acc = 0.f;
#pragma unroll
        for (int j = 0; j < 10; j++) acc = fmaf(g_invA[i * 10 + j], a[j], acc);
        out[r * 10 + i] = acc;
    }
}

// ---------------------------------------------------------------------------

extern "C" void kernel_launch(void* const* d_in, const int* in_sizes, int n_in,
                              void* d_out, int out_size) {
    const float* x = (const float*)d_in[0];   // [B, 10]
    const float* A = (const float*)d_in[1];   // [10, 10]
    float* out = (float*)d_out;

    const int n_elems = in_sizes[0];
    const int nrows   = n_elems / 10;
    const int npairs  = nrows / 2;

    invert10_kernel<<<1, 32>>>(A);

    if (npairs > 0) {
        const int threads = 256;
        const int blocks  = (npairs + threads - 1) / threads;
        solve_kernel<<<blocks, threads>>>((const float4*)x, (float4*)out, npairs);
    }
    if (nrows & 1) {
        tail_kernel<<<1, 32>>>(x, out, npairs * 2, nrows);
    }
}

// round 7
// speedup vs baseline: 1.0023x; 1.0008x over previous
#include <cuda_runtime.h>
#include <cuda_bf16.h>
#include <cstdint>

// ---------------------------------------------------------------------------
// out[b,:] = A^{-1} @ x[b,:],  B = 2e6, N = 10.
//   K1: one-warp fp32 Gauss-Jordan (partial pivot) + Newton polish -> invA
//       (plain + padded 12-float-stride copy for vectorized LDS).
//   K2: per-warp smem staging (coalesced LDG/STG), 2 rows/thread,
//       float4-vectorized weight loads (3x LDS.128 per output row).
// ---------------------------------------------------------------------------

__device__ float g_invA[100];    // A^{-1}, row-major (tail path)
__device__ float g_invAp[120];   // padded: row i at 12*i, [10],[11] = 0

// ---------------------------- Kernel 1: inversion ---------------------------

__global__ void invert10_kernel(const float* __restrict__ A) {
    const unsigned FULL = 0xffffffffu;
    const int lane = threadIdx.x;

    float arow[10];   // original A row (for Newton polish)
    float row[20];    // augmented [A | I]
#pragma unroll
    for (int j = 0; j < 10; j++) arow[j] = 0.f;
#pragma unroll
    for (int j = 0; j < 20; j++) row[j] = 0.f;
    if (lane < 10) {
#pragma unroll
        for (int j = 0; j < 10; j++) { arow[j] = A[lane * 10 + j]; row[j] = arow[j]; }
#pragma unroll
        for (int j = 0; j < 10; j++) row[10 + j] = (lane == j) ? 1.f : 0.f;
    }

#pragma unroll
    for (int k = 0; k < 10; k++) {
        // argmax |row[k]| over lanes k..9
        float v = (lane >= k && lane < 10) ? fabsf(row[k]) : -1.f;
        int best = lane;
#pragma unroll
        for (int off = 16; off; off >>= 1) {
            float ov = __shfl_xor_sync(FULL, v, off);
            int   ob = __shfl_xor_sync(FULL, best, off);
            if (ov > v || (ov == v && ob < best)) { v = ov; best = ob; }
        }
        const int piv = best;

        // swap rows k <-> piv
#pragma unroll
        for (int j = 0; j < 20; j++) {
            float vk = __shfl_sync(FULL, row[j], k);
            float vp = __shfl_sync(FULL, row[j], piv);
            if (piv != k) {
                if (lane == k)   row[j] = vp;
                if (lane == piv) row[j] = vk;
            }
        }

        // eliminate
        float pr[20];
#pragma unroll
        for (int j = 0; j < 20; j++) pr[j] = __shfl_sync(FULL, row[j], k);
        const float pinv = 1.f / pr[k];
        if (lane < 10) {
            if (lane == k) {
#pragma unroll
                for (int j = 0; j < 20; j++) row[j] *= pinv;
            } else {
                const float f = row[k] * pinv;
#pragma unroll
                for (int j = 0; j < 20; j++) row[j] = fmaf(-f, pr[j], row[j]);
            }
        }
    }

    float x0[10];
#pragma unroll
    for (int j = 0; j < 10; j++) x0[j] = row[10 + j];

    // Newton polish: X1 = X0 (2I - A X0).
    float e[10];
#pragma unroll
    for (int j = 0; j < 10; j++) e[j] = (lane == j) ? 2.f : 0.f;
#pragma unroll
    for (int k = 0; k < 10; k++) {
        const float ak = arow[k];
#pragma unroll
        for (int j = 0; j < 10; j++) {
            float xkj = __shfl_sync(FULL, x0[j], k);
            e[j] = fmaf(-ak, xkj, e[j]);
        }
    }
    float x1[10];
#pragma unroll
    for (int j = 0; j < 10; j++) x1[j] = 0.f;
#pragma unroll
    for (int k = 0; k < 10; k++) {
        const float xk = x0[k];
#pragma unroll
        for (int j = 0; j < 10; j++) {
            float ekj = __shfl_sync(FULL, e[j], k);
            x1[j] = fmaf(xk, ekj, x1[j]);
        }
    }

    if (lane < 10) {
#pragma unroll
        for (int j = 0; j < 10; j++) g_invA[lane * 10 + j] = x1[j];
#pragma unroll
        for (int j = 0; j < 10; j++) g_invAp[lane * 12 + j] = x1[j];
        g_invAp[lane * 12 + 10] = 0.f;
        g_invAp[lane * 12 + 11] = 0.f;
    }
}

// ------------------------- Kernel 2: streaming solve ------------------------
// Warp tile: 32 pairs = 64 rows = 2560 B. Coalesced global access both ways;
// per-warp smem region for redistribution. Weights read as float4 (3 LDS.128
// per output row instead of 10 scalar LDS.32).

__global__ void __launch_bounds__(256, 4) solve_kernel(
    const float4* __restrict__ x4, float4* __restrict__ o4, int npairs) {

    __shared__ float4 sbuf[8 * 160];              // 20 KB
    __shared__ __align__(16) float sw[120];       // padded weights

    const int t    = threadIdx.x;
    const int warp = t >> 5;
    const int lane = t & 31;
    const int pairBase = blockIdx.x * 256 + warp * 32;
    float4* wb = sbuf + warp * 160;

    if (t < 120) sw[t] = g_invAp[t];
    __syncthreads();

    const bool full = (pairBase + 32 <= npairs);
    const bool inRange = (pairBase + lane) < npairs;

    float4 v0, v1, v2, v3, v4;
    v0 = v1 = v2 = v3 = v4 = make_float4(0.f, 0.f, 0.f, 0.f);

    if (full) {
        const size_t f4base = (size_t)pairBase * 5;
#pragma unroll
        for (int s = 0; s < 5; s++)
            wb[lane + 32 * s] = __ldcs(x4 + f4base + lane + 32 * s);
        __syncwarp();
        v0 = wb[5 * lane + 0];
        v1 = wb[5 * lane + 1];
        v2 = wb[5 * lane + 2];
        v3 = wb[5 * lane + 3];
        v4 = wb[5 * lane + 4];
    } else if (inRange) {
        const float4* p = x4 + (size_t)(pairBase + lane) * 5;
        v0 = __ldcs(p + 0); v1 = __ldcs(p + 1); v2 = __ldcs(p + 2);
        v3 = __ldcs(p + 3); v4 = __ldcs(p + 4);
    }

    const float a0[10] = { v0.x, v0.y, v0.z, v0.w, v1.x, v1.y, v1.z, v1.w, v2.x, v2.y };
    const float a1[10] = { v2.z, v2.w, v3.x, v3.y, v3.z, v3.w, v4.x, v4.y, v4.z, v4.w };

    float r0[10], r1[10];
#pragma unroll
    for (int i = 0; i < 10; i++) {
        const float4 wa  = *(const float4*)(sw + 12 * i);      // w[i][0..3]
        const float4 wbv = *(const float4*)(sw + 12 * i + 4);  // w[i][4..7]
        const float4 wc  = *(const float4*)(sw + 12 * i + 8);  // w[i][8..9], pad
        float acc0, acc1;
        acc0 = wa.x * a0[0];             acc1 = wa.x * a1[0];
        acc0 = fmaf(wa.y, a0[1], acc0);  acc1 = fmaf(wa.y, a1[1], acc1);
        acc0 = fmaf(wa.z, a0[2], acc0);  acc1 = fmaf(wa.z, a1[2], acc1);
        acc0 = fmaf(wa.w, a0[3], acc0);  acc1 = fmaf(wa.w, a1[3], acc1);
        acc0 = fmaf(wbv.x, a0[4], acc0); acc1 = fmaf(wbv.x, a1[4], acc1);
        acc0 = fmaf(wbv.y, a0[5], acc0); acc1 = fmaf(wbv.y, a1[5], acc1);
        acc0 = fmaf(wbv.z, a0[6], acc0); acc1 = fmaf(wbv.z, a1[6], acc1);
        acc0 = fmaf(wbv.w, a0[7], acc0); acc1 = fmaf(wbv.w, a1[7], acc1);
        acc0 = fmaf(wc.x, a0[8], acc0);  acc1 = fmaf(wc.x, a1[8], acc1);
        acc0 = fmaf(wc.y, a0[9], acc0);  acc1 = fmaf(wc.y, a1[9], acc1);
        r0[i] = acc0;
        r1[i] = acc1;
    }

    if (full) {
        const size_t f4base = (size_t)pairBase * 5;
        wb[5 * lane + 0] = make_float4(r0[0], r0[1], r0[2], r0[3]);
        wb[5 * lane + 1] = make_float4(r0[4], r0[5], r0[6], r0[7]);
        wb[5 * lane + 2] = make_float4(r0[8], r0[9], r1[0], r1[1]);
        wb[5 * lane + 3] = make_float4(r1[2], r1[3], r1[4], r1[5]);
        wb[5 * lane + 4] = make_float4(r1[6], r1[7], r1[8], r1[9]);
        __syncwarp();
#pragma unroll
        for (int s = 0; s < 5; s++)
            __stcs(o4 + f4base + lane + 32 * s, wb[lane + 32 * s]);
    } else if (inRange) {
        float4* q = o4 + (size_t)(pairBase + lane) * 5;
        __stcs(q + 0, make_float4(r0[0], r0[1], r0[2], r0[3]));
        __stcs(q + 1, make_float4(r0[4], r0[5], r0[6], r0[7]));
        __stcs(q + 2, make_float4(r0[8], r0[9], r1[0], r1[1]));
        __stcs(q + 3, make_float4(r1[2], r1[3], r1[4], r1[5]));
        __stcs(q + 4, make_float4(r1[6], r1[7], r1[8], r1[9]));
    }
}

// ----------------------- Tail: odd leftover row (safety) --------------------

__global__ void tail_kernel(const float* __restrict__ x, float* __restrict__ out,
                            int rowstart, int nrows) {
    int r = rowstart + blockIdx.x * blockDim.x + threadIdx.x;
    if (r >= nrows) return;
    float a[10];
#pragma unroll
    for (int j = 0; j < 10; j++) a[j] = x[r * 10 + j];
#pragma unroll
    for (int i = 0; i < 10; i++) {
        float acc = 0.f;
#pragma unroll
        for (int j = 0; j < 10; j++) acc = fmaf(g_invA[i * 10 + j], a[j], acc);
        out[r * 10 + i] = acc;
    }
}

// ---------------------------------------------------------------------------

extern "C" void kernel_launch(void* const* d_in, const int* in_sizes, int n_in,
                              void* d_out, int out_size) {
    const float* x = (const float*)d_in[0];   // [B, 10]
    const float* A = (const float*)d_in[1];   // [10, 10]
    float* out = (float*)d_out;

    const int n_elems = in_sizes[0];
    const int nrows   = n_elems / 10;
    const int npairs  = nrows / 2;

    invert10_kernel<<<1, 32>>>(A);

    if (npairs > 0) {
        const int threads = 256;
        const int blocks  = (npairs + threads - 1) / threads;
        solve_kernel<<<blocks, threads>>>((const float4*)x, (float4*)out, npairs);
    }
    if (nrows & 1) {
        tail_kernel<<<1, 32>>>(x, out, npairs * 2, nrows);
    }
}

// round 8
// speedup vs baseline: 1.0363x; 1.0339x over previous
#include <cuda_runtime.h>
#include <cuda_bf16.h>
#include <cstdint>

// ---------------------------------------------------------------------------
// out[b,:] = A^{-1} @ x[b,:],  B = 2e6, N = 10.
//   K1: one-warp fp32 Gauss-Jordan (partial pivot) + Newton polish -> invA.
//   K2: CTA tile of 256 pairs (20480 B). cp.async.bulk (TMA 1D) fills smem,
//       threads compute 2 rows each from smem, results staged to smem,
//       cp.async.bulk stores back. PDL overlaps K2's input fill with K1.
// ---------------------------------------------------------------------------

__device__ float g_invA[100];    // A^{-1}, row-major (tail path)
__device__ float g_invAp[120];   // padded: row i at 12*i, [10],[11] = 0

// ---------------------------- Kernel 1: inversion ---------------------------

__global__ void invert10_kernel(const float* __restrict__ A) {
    const unsigned FULL = 0xffffffffu;
    const int lane = threadIdx.x;

    float arow[10];
    float row[20];
#pragma unroll
    for (int j = 0; j < 10; j++) arow[j] = 0.f;
#pragma unroll
    for (int j = 0; j < 20; j++) row[j] = 0.f;
    if (lane < 10) {
#pragma unroll
        for (int j = 0; j < 10; j++) { arow[j] = A[lane * 10 + j]; row[j] = arow[j]; }
#pragma unroll
        for (int j = 0; j < 10; j++) row[10 + j] = (lane == j) ? 1.f : 0.f;
    }

#pragma unroll
    for (int k = 0; k < 10; k++) {
        float v = (lane >= k && lane < 10) ? fabsf(row[k]) : -1.f;
        int best = lane;
#pragma unroll
        for (int off = 16; off; off >>= 1) {
            float ov = __shfl_xor_sync(FULL, v, off);
            int   ob = __shfl_xor_sync(FULL, best, off);
            if (ov > v || (ov == v && ob < best)) { v = ov; best = ob; }
        }
        const int piv = best;

#pragma unroll
        for (int j = 0; j < 20; j++) {
            float vk = __shfl_sync(FULL, row[j], k);
            float vp = __shfl_sync(FULL, row[j], piv);
            if (piv != k) {
                if (lane == k)   row[j] = vp;
                if (lane == piv) row[j] = vk;
            }
        }

        float pr[20];
#pragma unroll
        for (int j = 0; j < 20; j++) pr[j] = __shfl_sync(FULL, row[j], k);
        const float pinv = 1.f / pr[k];
        if (lane < 10) {
            if (lane == k) {
#pragma unroll
                for (int j = 0; j < 20; j++) row[j] *= pinv;
            } else {
                const float f = row[k] * pinv;
#pragma unroll
                for (int j = 0; j < 20; j++) row[j] = fmaf(-f, pr[j], row[j]);
            }
        }
    }

    float x0[10];
#pragma unroll
    for (int j = 0; j < 10; j++) x0[j] = row[10 + j];

    // Newton polish: X1 = X0 (2I - A X0).
    float e[10];
#pragma unroll
    for (int j = 0; j < 10; j++) e[j] = (lane == j) ? 2.f : 0.f;
#pragma unroll
    for (int k = 0; k < 10; k++) {
        const float ak = arow[k];
#pragma unroll
        for (int j = 0; j < 10; j++) {
            float xkj = __shfl_sync(FULL, x0[j], k);
            e[j] = fmaf(-ak, xkj, e[j]);
        }
    }
    float x1[10];
#pragma unroll
    for (int j = 0; j < 10; j++) x1[j] = 0.f;
#pragma unroll
    for (int k = 0; k < 10; k++) {
        const float xk = x0[k];
#pragma unroll
        for (int j = 0; j < 10; j++) {
            float ekj = __shfl_sync(FULL, e[j], k);
            x1[j] = fmaf(xk, ekj, x1[j]);
        }
    }

    if (lane < 10) {
#pragma unroll
        for (int j = 0; j < 10; j++) g_invA[lane * 10 + j] = x1[j];
#pragma unroll
        for (int j = 0; j < 10; j++) g_invAp[lane * 12 + j] = x1[j];
        g_invAp[lane * 12 + 10] = 0.f;
        g_invAp[lane * 12 + 11] = 0.f;
    }
}

// --------------------------- PTX helpers (K2) -------------------------------

__device__ __forceinline__ uint32_t smem_u32(const void* p) {
    uint32_t a;
    asm("{ .reg .u64 t; cvta.to.shared.u64 t, %1; cvt.u32.u64 %0, t; }"
        : "=r"(a) : "l"(p));
    return a;
}
__device__ __forceinline__ void mbar_init(uint32_t mbar, uint32_t count) {
    asm volatile("mbarrier.init.shared.b64 [%0], %1;" :: "r"(mbar), "r"(count) : "memory");
}
__device__ __forceinline__ void mbar_expect_tx(uint32_t mbar, uint32_t bytes) {
    asm volatile("mbarrier.arrive.expect_tx.shared.b64 _, [%0], %1;"
                 :: "r"(mbar), "r"(bytes) : "memory");
}
__device__ __forceinline__ void mbar_wait_parity(uint32_t mbar, uint32_t parity) {
    asm volatile(
        "{\n\t"
        ".reg .pred P;\n\t"
        "WAIT_%=:\n\t"
        "mbarrier.try_wait.parity.shared::cta.b64 P, [%0], %1;\n\t"
        "@!P bra WAIT_%=;\n\t"
        "}"
        :: "r"(mbar), "r"(parity) : "memory");
}
__device__ __forceinline__ void tma_load_1d(uint32_t smem_dst, const void* gsrc,
                                            uint32_t bytes, uint32_t mbar) {
    asm volatile(
        "cp.async.bulk.shared::cta.global.mbarrier::complete_tx::bytes "
        "[%0], [%1], %2, [%3];"
        :: "r"(smem_dst), "l"(gsrc), "r"(bytes), "r"(mbar) : "memory");
}
__device__ __forceinline__ void tma_store_1d(void* gdst, uint32_t smem_src,
                                             uint32_t bytes) {
    asm volatile(
        "cp.async.bulk.global.shared::cta.bulk_group [%0], [%1], %2;"
        :: "l"(gdst), "r"(smem_src), "r"(bytes) : "memory");
}

// ------------------------- Kernel 2: streaming solve ------------------------
// CTA tile: 256 pairs = 512 rows = 20480 B in and out.

#define TILE_PAIRS 256
#define TILE_BYTES (TILE_PAIRS * 80)

__global__ void __launch_bounds__(256, 4) solve_kernel(
    const float* __restrict__ x, float* __restrict__ o, int npairs) {

    __shared__ __align__(128) float4 sin[TILE_PAIRS * 5];   // 20480 B
    __shared__ __align__(128) float4 sout[TILE_PAIRS * 5];  // 20480 B
    __shared__ __align__(16)  float  sw[120];
    __shared__ __align__(8)   unsigned long long mbar_store;

    const int t = threadIdx.x;
    const int pairBase = blockIdx.x * TILE_PAIRS;
    const int cnt = min(TILE_PAIRS, npairs - pairBase);   // pairs this CTA
    const uint32_t bytes = (uint32_t)cnt * 80u;

    const uint32_t mbar = smem_u32(&mbar_store);
    if (t == 0) mbar_init(mbar, 1);
    __syncthreads();

    // Issue the input fill FIRST — x does not depend on invert10_kernel.
    if (t == 0) {
        mbar_expect_tx(mbar, bytes);
        tma_load_1d(smem_u32(sin), x + (size_t)pairBase * 20, bytes, mbar);
    }

    // Now wait for invert10_kernel (PDL) and pull the weights.
    asm volatile("griddepcontrol.wait;" ::: "memory");
    if (t < 120) sw[t] = g_invAp[t];
    __syncthreads();

    // Wait for tile data.
    mbar_wait_parity(mbar, 0);

    if (t < cnt) {
        const float4 v0 = sin[5 * t + 0];
        const float4 v1 = sin[5 * t + 1];
        const float4 v2 = sin[5 * t + 2];
        const float4 v3 = sin[5 * t + 3];
        const float4 v4 = sin[5 * t + 4];

        const float a0[10] = { v0.x, v0.y, v0.z, v0.w, v1.x, v1.y, v1.z, v1.w, v2.x, v2.y };
        const float a1[10] = { v2.z, v2.w, v3.x, v3.y, v3.z, v3.w, v4.x, v4.y, v4.z, v4.w };

        float r0[10], r1[10];
#pragma unroll
        for (int i = 0; i < 10; i++) {
            const float4 wa  = *(const float4*)(sw + 12 * i);
            const float4 wbv = *(const float4*)(sw + 12 * i + 4);
            const float4 wc  = *(const float4*)(sw + 12 * i + 8);
            float acc0, acc1;
            acc0 = wa.x * a0[0];             acc1 = wa.x * a1[0];
            acc0 = fmaf(wa.y, a0[1], acc0);  acc1 = fmaf(wa.y, a1[1], acc1);
            acc0 = fmaf(wa.z, a0[2], acc0);  acc1 = fmaf(wa.z, a1[2], acc1);
            acc0 = fmaf(wa.w, a0[3], acc0);  acc1 = fmaf(wa.w, a1[3], acc1);
            acc0 = fmaf(wbv.x, a0[4], acc0); acc1 = fmaf(wbv.x, a1[4], acc1);
            acc0 = fmaf(wbv.y, a0[5], acc0); acc1 = fmaf(wbv.y, a1[5], acc1);
            acc0 = fmaf(wbv.z, a0[6], acc0); acc1 = fmaf(wbv.z, a1[6], acc1);
            acc0 = fmaf(wbv.w, a0[7], acc0); acc1 = fmaf(wbv.w, a1[7], acc1);
            acc0 = fmaf(wc.x, a0[8], acc0);  acc1 = fmaf(wc.x, a1[8], acc1);
            acc0 = fmaf(wc.y, a0[9], acc0);  acc1 = fmaf(wc.y, a1[9], acc1);
            r0[i] = acc0;
            r1[i] = acc1;
        }

        sout[5 * t + 0] = make_float4(r0[0], r0[1], r0[2], r0[3]);
        sout[5 * t + 1] = make_float4(r0[4], r0[5], r0[6], r0[7]);
        sout[5 * t + 2] = make_float4(r0[8], r0[9], r1[0], r1[1]);
        sout[5 * t + 3] = make_float4(r1[2], r1[3], r1[4], r1[5]);
        sout[5 * t + 4] = make_float4(r1[6], r1[7], r1[8], r1[9]);
    }

    // Order generic-proxy smem writes before the async-proxy bulk store.
    __syncthreads();
    if (t == 0) {
        asm volatile("fence.proxy.async.shared::cta;" ::: "memory");
        tma_store_1d(o + (size_t)pairBase * 20, smem_u32(sout), bytes);
        asm volatile("cp.async.bulk.commit_group;" ::: "memory");
        asm volatile("cp.async.bulk.wait_group 0;" ::: "memory");
    }
}

// ----------------------- Tail: odd leftover row (safety) --------------------

__global__ void tail_kernel(const float* __restrict__ x, float* __restrict__ out,
                            int rowstart, int nrows) {
    int r = rowstart + blockIdx.x * blockDim.x + threadIdx.x;
    if (r >= nrows) return;
    float a[10];
#pragma unroll
    for (int j = 0; j < 10; j++) a[j] = x[r * 10 + j];
#pragma unroll
    for (int i = 0; i < 10; i++) {
        float acc = 0.f;
#pragma unroll
        for (int j = 0; j < 10; j++) acc = fmaf(g_invA[i * 10 + j], a[j], acc);
        out[r * 10 + i] = acc;
    }
}

// ---------------------------------------------------------------------------

extern "C" void kernel_launch(void* const* d_in, const int* in_sizes, int n_in,
                              void* d_out, int out_size) {
    const float* x = (const float*)d_in[0];   // [B, 10]
    const float* A = (const float*)d_in[1];   // [10, 10]
    float* out = (float*)d_out;

    const int n_elems = in_sizes[0];
    const int nrows   = n_elems / 10;
    const int npairs  = nrows / 2;

    invert10_kernel<<<1, 32>>>(A);

    if (npairs > 0) {
        const int blocks = (npairs + TILE_PAIRS - 1) / TILE_PAIRS;

        // PDL: solve may begin (and issue its TMA input fills) before invert
        // completes; it waits via griddepcontrol.wait before reading weights.
        cudaLaunchConfig_t cfg = {};
        cfg.gridDim  = dim3((unsigned)blocks, 1, 1);
        cfg.blockDim = dim3(256, 1, 1);
        cfg.dynamicSmemBytes = 0;
        cfg.stream = 0;
        cudaLaunchAttribute attrs[1];
        attrs[0].id = cudaLaunchAttributeProgrammaticStreamSerialization;
        attrs[0].val.programmaticStreamSerializationAllowed = 1;
        cfg.attrs = attrs;
        cfg.numAttrs = 1;
        cudaLaunchKernelEx(&cfg, solve_kernel, x, out, npairs);
    }
    if (nrows & 1) {
        tail_kernel<<<1, 32>>>(x, out, npairs * 2, nrows);
    }
}